// round 11
// baseline (speedup 1.0000x reference)
#include <cuda_runtime.h>
#include <math.h>
#include <stdint.h>

// Problem constants (fixed by the reference)
#define BATCH 2
#define SEQ   1024
#define HID   4096
#define NHEAD 32
#define HD    128
#define QKVN  (3 * HID)              // 12288
#define MROWS (BATCH * SEQ)          // 2048
#define INV_NORM 0.08838834764831845f // 1/sqrt(128)

// Scratch (device globals: allocation-guard safe)
__device__ float g_qkv[(size_t)MROWS * QKVN];  // [2048, 12288]
__device__ float g_ctx[(size_t)MROWS * HID];   // [2048, 4096]

// ---------------------------------------------------------------------------
// mma helpers (m16n8k16 bf16, fp32 accumulate). C-frag == m16n8k8 layout.
// a-frag: a0=(row gid, k=2tig,2tig+1) a1=(row gid+8, same k)
//         a2=(row gid, k=2tig+8,+9)   a3=(row gid+8, same k)
// b-frag: b0=(k=2tig,2tig+1, n=gid)   b1=(k=2tig+8,+9, n=gid)
// packed word: low half = even-k element, high half = odd-k element.
// ---------------------------------------------------------------------------
__device__ __forceinline__ void mma_bf16(float* c, const unsigned* a, const unsigned* b) {
    asm volatile(
        "mma.sync.aligned.m16n8k16.row.col.f32.bf16.bf16.f32 "
        "{%0,%1,%2,%3}, {%4,%5,%6,%7}, {%8,%9}, {%0,%1,%2,%3};\n"
        : "+f"(c[0]), "+f"(c[1]), "+f"(c[2]), "+f"(c[3])
        : "r"(a[0]), "r"(a[1]), "r"(a[2]), "r"(a[3]), "r"(b[0]), "r"(b[1]));
}

// Pack two fp32 into bf16x2: low half = even-k element, high half = odd-k.
__device__ __forceinline__ unsigned pack_bf16(float even_e, float odd_e) {
    unsigned d;
    asm("cvt.rn.bf16x2.f32 %0, %1, %2;" : "=r"(d) : "f"(odd_e), "f"(even_e));
    return d;
}

// Split pair (x0=even, x1=odd) into bf16x2 hi word + bf16x2 lo word.
__device__ __forceinline__ void bf16_split2(float x0, float x1, unsigned& h, unsigned& l) {
    h = pack_bf16(x0, x1);
    const float h0 = __uint_as_float(h << 16);         // even element as f32
    const float h1 = __uint_as_float(h & 0xFFFF0000u); // odd element as f32
    l = pack_bf16(x0 - h0, x1 - h1);
}

// ---------------------------------------------------------------------------
// bf16x3 tensor-core GEMM: C[M,N] = A[M,K] @ B[K,N] + bias[N] (+ resid)
// fp32-class accuracy via hi/lo split: A*B ~= Ah*Bh + Ah*Bl + Al*Bh (~5e-6 rel).
// 128x128 block tile, BK=16 (= one m16n8k16 step), 256 threads = 8 warps
// (4m x 2n), warp tile 32x64. Double-buffered smem, one barrier per K-tile.
// A planes [m][k2] stride 12 (frag banks 12g+t: conflict-free);
// B planes [k2][n] stride 136 (frag banks 8t+g: conflict-free).
// ---------------------------------------------------------------------------
#define GA_S 12                         // A plane row stride (words)
#define GB_S 136                        // B plane row stride (words)
#define GA_W (128 * GA_S)               // 1536 words per A plane
#define GB_W (8 * GB_S)                 // 1088 words per B plane
#define GBUF_W (2 * GA_W + 2 * GB_W)    // one buffer: AsH,AsL,BsH,BsL
#define GEMM_SMEM_BYTES (2 * GBUF_W * 4)

template<bool RESID>
__global__ __launch_bounds__(256) void bf16_gemm(
    const float* __restrict__ A, const float* __restrict__ Bm,
    const float* __restrict__ bias, const float* __restrict__ resid,
    float* __restrict__ C, int M, int N, int K)
{
    extern __shared__ unsigned smg[];

    const int t    = threadIdx.x;
    const int lane = t & 31;
    const int w    = t >> 5;
    const int wm   = w & 3;
    const int wn   = w >> 2;
    const int gid  = lane >> 2;
    const int tig  = lane & 3;
    const int row0 = blockIdx.y * 128;
    const int col0 = blockIdx.x * 128;

    // Loader coords. A: 2 float4/thread (rows a_r0,a_r1; k cols a_c0..+3).
    // B: 2 float4/thread from adjacent k-rows 2p,2p+1 (enables k-packing).
    const int a_r0 = t >> 2;              // 0..63
    const int a_c0 = (t & 3) << 2;        // 0,4,8,12
    const int a_r1 = a_r0 + 64;
    const int b_p  = t >> 5;              // k-pair 0..7
    const int b_c  = (t & 31) << 2;       // 0..124

    const float* Ap0 = A  + (size_t)(row0 + a_r0) * K + a_c0;
    const float* Ap1 = A  + (size_t)(row0 + a_r1) * K + a_c0;
    const float* Bp0 = Bm + (size_t)(2 * b_p) * N + col0 + b_c;
    const float* Bp1 = Bm + (size_t)(2 * b_p + 1) * N + col0 + b_c;

    float acc[2][8][4];
    #pragma unroll
    for (int mf = 0; mf < 2; mf++)
        #pragma unroll
        for (int nf = 0; nf < 8; nf++)
            #pragma unroll
            for (int r = 0; r < 4; r++) acc[mf][nf][r] = 0.0f;

#define G_STORE_TILE(BUF, AV0, AV1, BV0, BV1)                                  \
    {                                                                          \
        unsigned* ASH = smg + (BUF) * GBUF_W;                                  \
        unsigned* ASL = ASH + GA_W;                                            \
        unsigned* BSH = ASH + 2 * GA_W;                                        \
        unsigned* BSL = BSH + GB_W;                                            \
        uint2 h2, l2;                                                          \
        bf16_split2(AV0.x, AV0.y, h2.x, l2.x);                                 \
        bf16_split2(AV0.z, AV0.w, h2.y, l2.y);                                 \
        *(uint2*)&ASH[a_r0 * GA_S + (a_c0 >> 1)] = h2;                         \
        *(uint2*)&ASL[a_r0 * GA_S + (a_c0 >> 1)] = l2;                         \
        bf16_split2(AV1.x, AV1.y, h2.x, l2.x);                                 \
        bf16_split2(AV1.z, AV1.w, h2.y, l2.y);                                 \
        *(uint2*)&ASH[a_r1 * GA_S + (a_c0 >> 1)] = h2;                         \
        *(uint2*)&ASL[a_r1 * GA_S + (a_c0 >> 1)] = l2;                         \
        uint4 h4, l4;                                                          \
        bf16_split2(BV0.x, BV1.x, h4.x, l4.x);                                 \
        bf16_split2(BV0.y, BV1.y, h4.y, l4.y);                                 \
        bf16_split2(BV0.z, BV1.z, h4.z, l4.z);                                 \
        bf16_split2(BV0.w, BV1.w, h4.w, l4.w);                                 \
        *(uint4*)&BSH[b_p * GB_S + b_c] = h4;                                  \
        *(uint4*)&BSL[b_p * GB_S + b_c] = l4;                                  \
    }

    // Prologue: tile 0 -> buffer 0
    {
        float4 av0 = *(const float4*)(Ap0);
        float4 av1 = *(const float4*)(Ap1);
        float4 bv0 = *(const float4*)(Bp0);
        float4 bv1 = *(const float4*)(Bp1);
        G_STORE_TILE(0, av0, av1, bv0, bv1);
    }
    __syncthreads();

    int buf = 0;
    for (int k0 = 0; k0 < K; k0 += 16) {
        const int kn = k0 + 16;
        const bool more = (kn < K);
        float4 av0, av1, bv0, bv1;
        if (more) {
            av0 = *(const float4*)(Ap0 + kn);
            av1 = *(const float4*)(Ap1 + kn);
            bv0 = *(const float4*)(Bp0 + (size_t)kn * N);
            bv1 = *(const float4*)(Bp1 + (size_t)kn * N);
        }

        const unsigned* ASH = smg + buf * GBUF_W;
        const unsigned* ASL = ASH + GA_W;
        const unsigned* BSH = ASH + 2 * GA_W;
        const unsigned* BSL = BSH + GB_W;

        // One m16n8k16 step covers the whole BK=16 tile.
        unsigned ah[2][4], al[2][4], bh[8][2], bl[8][2];
        #pragma unroll
        for (int mf = 0; mf < 2; mf++) {
            const int m = wm * 32 + mf * 16 + gid;
            ah[mf][0] = ASH[m * GA_S + tig];
            ah[mf][1] = ASH[(m + 8) * GA_S + tig];
            ah[mf][2] = ASH[m * GA_S + tig + 4];
            ah[mf][3] = ASH[(m + 8) * GA_S + tig + 4];
            al[mf][0] = ASL[m * GA_S + tig];
            al[mf][1] = ASL[(m + 8) * GA_S + tig];
            al[mf][2] = ASL[m * GA_S + tig + 4];
            al[mf][3] = ASL[(m + 8) * GA_S + tig + 4];
        }
        #pragma unroll
        for (int nf = 0; nf < 8; nf++) {
            const int n = wn * 64 + nf * 8 + gid;
            bh[nf][0] = BSH[tig * GB_S + n];
            bh[nf][1] = BSH[(tig + 4) * GB_S + n];
            bl[nf][0] = BSL[tig * GB_S + n];
            bl[nf][1] = BSL[(tig + 4) * GB_S + n];
        }
        #pragma unroll
        for (int mf = 0; mf < 2; mf++)
            #pragma unroll
            for (int nf = 0; nf < 8; nf++) {
                mma_bf16(acc[mf][nf], ah[mf], bh[nf]);
                mma_bf16(acc[mf][nf], ah[mf], bl[nf]);
                mma_bf16(acc[mf][nf], al[mf], bh[nf]);
            }

        if (more) {
            G_STORE_TILE(buf ^ 1, av0, av1, bv0, bv1);
            __syncthreads();
        }
        buf ^= 1;
    }
#undef G_STORE_TILE

    // Epilogue: c0,c1 at (row, col..col+1); c2,c3 at (row+8, ...)
    #pragma unroll
    for (int mf = 0; mf < 2; mf++) {
        #pragma unroll
        for (int nf = 0; nf < 8; nf++) {
            const int row = row0 + wm * 32 + mf * 16 + gid;
            const int col = col0 + wn * 64 + nf * 8 + 2 * tig;
            const float b0 = bias[col], b1 = bias[col + 1];
            float2 o0, o1;
            o0.x = acc[mf][nf][0] + b0;
            o0.y = acc[mf][nf][1] + b1;
            o1.x = acc[mf][nf][2] + b0;
            o1.y = acc[mf][nf][3] + b1;
            if (RESID) {
                const float2 r0 = *(const float2*)(resid + (size_t)row * N + col);
                const float2 r1 = *(const float2*)(resid + (size_t)(row + 8) * N + col);
                o0.x += r0.x; o0.y += r0.y;
                o1.x += r1.x; o1.y += r1.y;
            }
            *(float2*)(C + (size_t)row * N + col) = o0;
            *(float2*)(C + (size_t)(row + 8) * N + col) = o1;
        }
    }
}

// ---------------------------------------------------------------------------
// Tensor-core flash attention, causal + alibi. BR=128, BC=64, HD=128,
// 8 warps x 16-row bands (warp-local softmax).
// S = Q@K^T: 1x bf16 m16n8k16 (alibi dominates scores; error ~3e-6 abs).
// P@V: bf16x3 m16n8k16. KEY IDENTITY: the m16n8k16 a-frag element pair
// (row gid, k=2tig,2tig+1) is exactly the S c-frag pair this lane owns,
// so P needs NO shuffles and NO smem: a0..a3 = packed S values directly.
// V packed [k2][n] stride 136 (hi/lo planes). K/V register-prefetched.
// ---------------------------------------------------------------------------
#define BR 128
#define BC 64
#define QPS 68                        // Qp row stride (words), [128][68]
#define KPS 68                        // Kp row stride (words), [64][68]
#define VPS 136                       // V plane row stride (words), [32][136]
#define QP_W (BR * QPS)               // 8704
#define KP_W (BC * KPS)               // 4352
#define VP_W (32 * VPS)               // 4352 per plane
#define AT_SMEM_BYTES ((QP_W + KP_W + 2 * VP_W) * 4)   // ~85 KB

__global__ __launch_bounds__(256, 1) void flash_attn_mma(const float* __restrict__ alibi)
{
    extern __shared__ unsigned smu[];
    unsigned* Qp  = smu;                 // [BR][QPS] bf16x2 pairs (k-dim)
    unsigned* Kp  = Qp + QP_W;           // [BC][KPS] bf16x2 pairs (k-dim)
    unsigned* VsH = Kp + KP_W;           // [32][VPS] bf16x2 hi pairs (k-dim)
    unsigned* VsL = VsH + VP_W;          // [32][VPS] bf16x2 lo pairs

    const int t    = threadIdx.x;
    const int lane = t & 31;
    const int w    = t >> 5;          // 0..7
    const int gid  = lane >> 2;       // 0..7
    const int tig  = lane & 3;        // 0..3
    const int band = w * 16;
    const int qt   = gridDim.x - 1 - blockIdx.x;   // heavy tiles first
    const int bh   = blockIdx.y;
    const int b    = bh >> 5;
    const int h    = bh & 31;
    const int q0   = qt * BR;

    const size_t rowbase = (size_t)(b * SEQ) * QKVN + (size_t)h * (3 * HD);
    const float* al = alibi + (size_t)bh * SEQ;

    const int kv_r  = t >> 5;              // 0..7 (warp id)
    const int kv_c4 = (t & 31) << 2;       // 0..124
    const int kv_k2 = kv_c4 >> 1;          // 0..62 even

    // Load Q tile: BR x HD -> packed bf16x2 (Qp[r][k2] = {Q[r][2k2], Q[r][2k2+1]})
    #pragma unroll
    for (int it = 0; it < 16; it++) {
        int idx = t + it * 256;            // 0..4095
        int r   = idx >> 5;                // 0..127
        int c4  = (idx & 31) << 2;         // 0..124
        float4 v = *(const float4*)(g_qkv + rowbase + (size_t)(q0 + r) * QKVN + c4);
        uint2 pw;
        pw.x = pack_bf16(v.x, v.y);
        pw.y = pack_bf16(v.z, v.w);
        *(uint2*)&Qp[r * QPS + (c4 >> 1)] = pw;
    }

    float O[16][4];
    #pragma unroll
    for (int nf = 0; nf < 16; nf++)
        #pragma unroll
        for (int r = 0; r < 4; r++) O[nf][r] = 0.0f;
    float m0 = -1e30f, m1 = -1e30f, l0 = 0.0f, l1 = 0.0f;

    // Prefetch registers: K rows {kv_r+8it, it<8}; V row-pairs {2p,2p+1},
    // p = kv_r + 8it, it<4 (pairs enable k-packing for the b-frag).
    float4 kp[8], vpa[4], vpb[4];
#define LOAD_KV(KBASE)                                                         \
    {                                                                          \
        _Pragma("unroll")                                                      \
        for (int it = 0; it < 8; it++) {                                       \
            const float* base = g_qkv + rowbase +                              \
                (size_t)((KBASE) + kv_r + it * 8) * QKVN;                      \
            kp[it] = *(const float4*)(base + HD + kv_c4);                      \
        }                                                                      \
        _Pragma("unroll")                                                      \
        for (int it = 0; it < 4; it++) {                                       \
            const int p = kv_r + it * 8;                                       \
            const float* vb = g_qkv + rowbase +                                \
                (size_t)((KBASE) + 2 * p) * QKVN + 2 * HD + kv_c4;             \
            vpa[it] = *(const float4*)(vb);                                    \
            vpb[it] = *(const float4*)(vb + QKVN);                             \
        }                                                                      \
    }

    LOAD_KV(0);   // prologue: tile 0 into registers

    const int kc_max = 2 * qt + 1;
    for (int kc = 0; kc <= kc_max; kc++) {
        const int kbase = kc * BC;
        __syncthreads();  // prev iter's K/V smem reads done (covers Q on iter 0)

        // Store prefetched tiles. K: bf16 pairs along HD. V: bf16x3 hi/lo
        // pairs along seq-k: word [p][n] = pack(V[2p][n], V[2p+1][n]).
        #pragma unroll
        for (int it = 0; it < 8; it++) {
            const int r = kv_r + it * 8;
            uint2 kw;
            kw.x = pack_bf16(kp[it].x, kp[it].y);
            kw.y = pack_bf16(kp[it].z, kp[it].w);
            *(uint2*)&Kp[r * KPS + kv_k2] = kw;
        }
        #pragma unroll
        for (int it = 0; it < 4; it++) {
            const int p = kv_r + it * 8;
            uint4 h4, l4;
            bf16_split2(vpa[it].x, vpb[it].x, h4.x, l4.x);
            bf16_split2(vpa[it].y, vpb[it].y, h4.y, l4.y);
            bf16_split2(vpa[it].z, vpb[it].z, h4.z, l4.z);
            bf16_split2(vpa[it].w, vpb[it].w, h4.w, l4.w);
            *(uint4*)&VsH[p * VPS + kv_c4] = h4;
            *(uint4*)&VsL[p * VPS + kv_c4] = l4;
        }
        __syncthreads();

        // Prefetch NEXT K/V tile (latency overlaps all compute below)
        if (kc < kc_max) LOAD_KV(kbase + BC);

        // --- S = Q @ K^T (1x bf16), rows band..band+15, cols 0..63 ---
        float S[8][4];
        #pragma unroll
        for (int nf = 0; nf < 8; nf++)
            #pragma unroll
            for (int r = 0; r < 4; r++) S[nf][r] = 0.0f;

        const int qb0 = (band + gid) * QPS;
        const int qb1 = qb0 + 8 * QPS;
        #pragma unroll
        for (int j = 0; j < 8; j++) {          // k16 steps over HD=128
            const int kk = 8 * j + tig;
            unsigned a[4];
            a[0] = Qp[qb0 + kk];
            a[1] = Qp[qb1 + kk];
            a[2] = Qp[qb0 + kk + 4];
            a[3] = Qp[qb1 + kk + 4];
            #pragma unroll
            for (int nf = 0; nf < 8; nf++) {
                const int nb = (nf * 8 + gid) * KPS;
                unsigned bfr[2];
                bfr[0] = Kp[nb + kk];
                bfr[1] = Kp[nb + kk + 4];
                mma_bf16(S[nf], a, bfr);
            }
        }

        // --- alibi + scale + causal mask + online softmax (warp-local) ---
        const int qr0 = q0 + band + gid;
        const int qr1 = qr0 + 8;
        float mx0 = -1e30f, mx1 = -1e30f;
        if (kc < 2 * qt) {
            // Interior tile: kbase+63 <= q0, no masking needed
            #pragma unroll
            for (int nf = 0; nf < 8; nf++) {
                const int c0 = kbase + nf * 8 + 2 * tig;
                const float a0 = al[c0], a1 = al[c0 + 1];
                S[nf][0] = fmaf(INV_NORM, S[nf][0], a0);
                S[nf][1] = fmaf(INV_NORM, S[nf][1], a1);
                S[nf][2] = fmaf(INV_NORM, S[nf][2], a0);
                S[nf][3] = fmaf(INV_NORM, S[nf][3], a1);
                mx0 = fmaxf(mx0, fmaxf(S[nf][0], S[nf][1]));
                mx1 = fmaxf(mx1, fmaxf(S[nf][2], S[nf][3]));
            }
        } else {
            #pragma unroll
            for (int nf = 0; nf < 8; nf++) {
                const int c0 = kbase + nf * 8 + 2 * tig;
                const float a0 = al[c0], a1 = al[c0 + 1];
                S[nf][0] = (c0     <= qr0) ? fmaf(INV_NORM, S[nf][0], a0) : -1e30f;
                S[nf][1] = (c0 + 1 <= qr0) ? fmaf(INV_NORM, S[nf][1], a1) : -1e30f;
                S[nf][2] = (c0     <= qr1) ? fmaf(INV_NORM, S[nf][2], a0) : -1e30f;
                S[nf][3] = (c0 + 1 <= qr1) ? fmaf(INV_NORM, S[nf][3], a1) : -1e30f;
                mx0 = fmaxf(mx0, fmaxf(S[nf][0], S[nf][1]));
                mx1 = fmaxf(mx1, fmaxf(S[nf][2], S[nf][3]));
            }
        }
        mx0 = fmaxf(mx0, __shfl_xor_sync(0xffffffffu, mx0, 1));
        mx0 = fmaxf(mx0, __shfl_xor_sync(0xffffffffu, mx0, 2));
        mx1 = fmaxf(mx1, __shfl_xor_sync(0xffffffffu, mx1, 1));
        mx1 = fmaxf(mx1, __shfl_xor_sync(0xffffffffu, mx1, 2));

        const float mn0 = fmaxf(m0, mx0);
        const float mn1 = fmaxf(m1, mx1);
        const float corr0 = __expf(m0 - mn0);
        const float corr1 = __expf(m1 - mn1);

        float rs0 = 0.0f, rs1 = 0.0f;
        #pragma unroll
        for (int nf = 0; nf < 8; nf++) {
            S[nf][0] = __expf(S[nf][0] - mn0);
            S[nf][1] = __expf(S[nf][1] - mn0);
            S[nf][2] = __expf(S[nf][2] - mn1);
            S[nf][3] = __expf(S[nf][3] - mn1);
            rs0 += S[nf][0] + S[nf][1];
            rs1 += S[nf][2] + S[nf][3];
        }
        rs0 += __shfl_xor_sync(0xffffffffu, rs0, 1);
        rs0 += __shfl_xor_sync(0xffffffffu, rs0, 2);
        rs1 += __shfl_xor_sync(0xffffffffu, rs1, 1);
        rs1 += __shfl_xor_sync(0xffffffffu, rs1, 2);

        l0 = l0 * corr0 + rs0; m0 = mn0;
        l1 = l1 * corr1 + rs1; m1 = mn1;
        #pragma unroll
        for (int nf = 0; nf < 16; nf++) {
            O[nf][0] *= corr0; O[nf][1] *= corr0;
            O[nf][2] *= corr1; O[nf][3] *= corr1;
        }

        // --- O += P @ V (bf16x3). P a-frag = this lane's own S values:
        // k16 step j covers cols 16j..16j+15 = S groups 2j, 2j+1; the pair
        // (k=2tig,2tig+1) is S[group][0..1] (row r0) / [2..3] (row r1). ---
        #pragma unroll
        for (int j = 0; j < 4; j++) {
            unsigned aph[4], apl[4];
            bf16_split2(S[2*j][0],   S[2*j][1],   aph[0], apl[0]);  // r0, k2=tig
            bf16_split2(S[2*j][2],   S[2*j][3],   aph[1], apl[1]);  // r1, k2=tig
            bf16_split2(S[2*j+1][0], S[2*j+1][1], aph[2], apl[2]);  // r0, k2=tig+4
            bf16_split2(S[2*j+1][2], S[2*j+1][3], aph[3], apl[3]);  // r1, k2=tig+4
            const int kb = 8 * j + tig;
            #pragma unroll
            for (int nf = 0; nf < 16; nf++) {
                const int n0 = nf * 8 + gid;
                unsigned bhf[2], blf[2];
                bhf[0] = VsH[kb * VPS + n0];
                bhf[1] = VsH[(kb + 4) * VPS + n0];
                blf[0] = VsL[kb * VPS + n0];
                blf[1] = VsL[(kb + 4) * VPS + n0];
                mma_bf16(O[nf], aph, bhf);
                mma_bf16(O[nf], aph, blf);
                mma_bf16(O[nf], apl, bhf);
            }
        }
    }
#undef LOAD_KV

    // Normalize and store ctx
    const float inv0 = 1.0f / l0;
    const float inv1 = 1.0f / l1;
    const size_t d0base = (size_t)(b * SEQ + q0 + band + gid) * HID + h * HD;
    const size_t d1base = (size_t)(b * SEQ + q0 + band + gid + 8) * HID + h * HD;
    #pragma unroll
    for (int nf = 0; nf < 16; nf++) {
        const int col = nf * 8 + 2 * tig;
        *(float2*)(g_ctx + d0base + col) = make_float2(O[nf][0] * inv0, O[nf][1] * inv0);
        *(float2*)(g_ctx + d1base + col) = make_float2(O[nf][2] * inv1, O[nf][3] * inv1);
    }
}

// ---------------------------------------------------------------------------
// Launch
// ---------------------------------------------------------------------------
extern "C" void kernel_launch(void* const* d_in, const int* in_sizes, int n_in,
                              void* d_out, int out_size)
{
    const float* hidden   = (const float*)d_in[0];
    const float* residual = (const float*)d_in[1];
    const float* alibi    = (const float*)d_in[2];
    // d_in[3] attention_mask: fixed causal triu — computed analytically, not read
    const float* W_qkv    = (const float*)d_in[4];
    const float* b_qkv    = (const float*)d_in[5];
    const float* W_dense  = (const float*)d_in[6];
    const float* b_dense  = (const float*)d_in[7];
    float* out = (float*)d_out;

    float* qkv_ptr = nullptr;
    float* ctx_ptr = nullptr;
    cudaGetSymbolAddress((void**)&qkv_ptr, g_qkv);
    cudaGetSymbolAddress((void**)&ctx_ptr, g_ctx);

    cudaFuncSetAttribute(bf16_gemm<false>, cudaFuncAttributeMaxDynamicSharedMemorySize,
                         GEMM_SMEM_BYTES);
    cudaFuncSetAttribute(bf16_gemm<true>, cudaFuncAttributeMaxDynamicSharedMemorySize,
                         GEMM_SMEM_BYTES);
    cudaFuncSetAttribute(flash_attn_mma, cudaFuncAttributeMaxDynamicSharedMemorySize,
                         AT_SMEM_BYTES);

    // 1) QKV projection: [2048,4096] @ [4096,12288] + b_qkv
    {
        dim3 grid(QKVN / 128, MROWS / 128);
        bf16_gemm<false><<<grid, 256, GEMM_SMEM_BYTES>>>(hidden, W_qkv, b_qkv, nullptr,
                                                         qkv_ptr, MROWS, QKVN, HID);
    }

    // 2) Attention (64 heads x 8 query tiles of 128 rows)
    {
        dim3 grid(SEQ / BR, BATCH * NHEAD);
        flash_attn_mma<<<grid, 256, AT_SMEM_BYTES>>>(alibi);
    }

    // 3) Dense projection + bias + residual
    {
        dim3 grid(HID / 128, MROWS / 128);
        bf16_gemm<true><<<grid, 256, GEMM_SMEM_BYTES>>>(ctx_ptr, W_dense, b_dense, residual,
                                                        out, MROWS, HID, HID);
    }
}

// round 13
// speedup vs baseline: 1.1551x; 1.1551x over previous
#include <cuda_runtime.h>
#include <math.h>
#include <stdint.h>

// Problem constants (fixed by the reference)
#define BATCH 2
#define SEQ   1024
#define HID   4096
#define NHEAD 32
#define HD    128
#define QKVN  (3 * HID)              // 12288
#define MROWS (BATCH * SEQ)          // 2048
#define INV_NORM 0.08838834764831845f // 1/sqrt(128)

// Scratch (device globals: allocation-guard safe)
__device__ float g_qkv[(size_t)MROWS * QKVN];  // [2048, 12288]
__device__ float g_ctx[(size_t)MROWS * HID];   // [2048, 4096]

// ---------------------------------------------------------------------------
// mma helpers (m16n8k16 bf16, fp32 accumulate). C-frag == m16n8k8 layout.
// packed word: low half = even-k element, high half = odd-k element.
// ---------------------------------------------------------------------------
__device__ __forceinline__ void mma_bf16(float* c, const unsigned* a, const unsigned* b) {
    asm volatile(
        "mma.sync.aligned.m16n8k16.row.col.f32.bf16.bf16.f32 "
        "{%0,%1,%2,%3}, {%4,%5,%6,%7}, {%8,%9}, {%0,%1,%2,%3};\n"
        : "+f"(c[0]), "+f"(c[1]), "+f"(c[2]), "+f"(c[3])
        : "r"(a[0]), "r"(a[1]), "r"(a[2]), "r"(a[3]), "r"(b[0]), "r"(b[1]));
}

// Pack two fp32 into bf16x2: low half = first (even) element.
__device__ __forceinline__ unsigned pack_bf16(float even_e, float odd_e) {
    unsigned d;
    asm("cvt.rn.bf16x2.f32 %0, %1, %2;" : "=r"(d) : "f"(odd_e), "f"(even_e));
    return d;
}

// Split pair (x0=even, x1=odd) into bf16x2 hi word + bf16x2 lo word.
__device__ __forceinline__ void bf16_split2(float x0, float x1, unsigned& h, unsigned& l) {
    h = pack_bf16(x0, x1);
    const float h0 = __uint_as_float(h << 16);         // even element as f32
    const float h1 = __uint_as_float(h & 0xFFFF0000u); // odd element as f32
    l = pack_bf16(x0 - h0, x1 - h1);
}

// ldmatrix wrappers (u32 shared-space addresses)
#define LDSM_X4(R0, R1, R2, R3, ADDR)                                          \
    asm volatile("ldmatrix.sync.aligned.m8n8.x4.shared.b16 {%0,%1,%2,%3}, [%4];" \
                 : "=r"(R0), "=r"(R1), "=r"(R2), "=r"(R3) : "r"(ADDR))
#define LDSM_X4_T(R0, R1, R2, R3, ADDR)                                        \
    asm volatile("ldmatrix.sync.aligned.m8n8.x4.trans.shared.b16 {%0,%1,%2,%3}, [%4];" \
                 : "=r"(R0), "=r"(R1), "=r"(R2), "=r"(R3) : "r"(ADDR))

// ---------------------------------------------------------------------------
// bf16x3 tensor-core GEMM: C[M,N] = A[M,K] @ B[K,N] + bias[N] (+ resid)
// fp32-class accuracy: A*B ~= Ah*Bh + Ah*Bl + Al*Bh (~5e-6 rel).
// 128x128 block tile, BK=16, 256 threads = 8 warps (4m x 2n), warp 32x64.
// ldmatrix fragment loads; 2 CTAs/SM.
// ---------------------------------------------------------------------------
#define GA_S 12                         // A plane row stride (words)
#define GB_S 68                         // B plane k-row stride (words)
#define GA_W (128 * GA_S)               // 1536 words per A plane
#define GB_W (16 * GB_S)                // 1088 words per B plane
#define GBUF_W (2 * GA_W + 2 * GB_W)    // one buffer: AsH,AsL,BsH,BsL
#define GEMM_SMEM_BYTES (2 * GBUF_W * 4)

template<bool RESID>
__global__ __launch_bounds__(256, 2) void bf16_gemm(
    const float* __restrict__ A, const float* __restrict__ Bm,
    const float* __restrict__ bias, const float* __restrict__ resid,
    float* __restrict__ C, int M, int N, int K)
{
    extern __shared__ unsigned smg[];
    const unsigned smem_u32 = (unsigned)__cvta_generic_to_shared(smg);

    const int t    = threadIdx.x;
    const int lane = t & 31;
    const int w    = t >> 5;
    const int wm   = w & 3;
    const int wn   = w >> 2;
    const int gid  = lane >> 2;
    const int tig  = lane & 3;
    const int row0 = blockIdx.y * 128;
    const int col0 = blockIdx.x * 128;

    const int a_r0 = t >> 2;              // 0..63
    const int a_c0 = (t & 3) << 2;        // 0,4,8,12
    const int a_r1 = a_r0 + 64;
    const int b_p  = t >> 5;              // k-pair 0..7
    const int b_c  = (t & 31) << 2;       // 0..124

    const float* Ap0 = A  + (size_t)(row0 + a_r0) * K + a_c0;
    const float* Ap1 = A  + (size_t)(row0 + a_r1) * K + a_c0;
    const float* Bp0 = Bm + (size_t)(2 * b_p) * N + col0 + b_c;
    const float* Bp1 = Bm + (size_t)(2 * b_p + 1) * N + col0 + b_c;

    float acc[2][8][4];
    #pragma unroll
    for (int mf = 0; mf < 2; mf++)
        #pragma unroll
        for (int nf = 0; nf < 8; nf++)
            #pragma unroll
            for (int r = 0; r < 4; r++) acc[mf][nf][r] = 0.0f;

    const int a_lm_row  = (lane & 15);
    const int a_lm_coff = (lane >> 4) << 2;
    const int b_lm_row  = (lane & 15);
    const int b_lm_noff = (lane >> 4) << 2;

#define G_STORE_TILE(BUF, AV0, AV1, BV0, BV1)                                  \
    {                                                                          \
        unsigned* ASH = smg + (BUF) * GBUF_W;                                  \
        unsigned* ASL = ASH + GA_W;                                            \
        unsigned* BSH = ASH + 2 * GA_W;                                        \
        unsigned* BSL = BSH + GB_W;                                            \
        uint2 h2, l2;                                                          \
        bf16_split2(AV0.x, AV0.y, h2.x, l2.x);                                 \
        bf16_split2(AV0.z, AV0.w, h2.y, l2.y);                                 \
        *(uint2*)&ASH[a_r0 * GA_S + (a_c0 >> 1)] = h2;                         \
        *(uint2*)&ASL[a_r0 * GA_S + (a_c0 >> 1)] = l2;                         \
        bf16_split2(AV1.x, AV1.y, h2.x, l2.x);                                 \
        bf16_split2(AV1.z, AV1.w, h2.y, l2.y);                                 \
        *(uint2*)&ASH[a_r1 * GA_S + (a_c0 >> 1)] = h2;                         \
        *(uint2*)&ASL[a_r1 * GA_S + (a_c0 >> 1)] = l2;                         \
        uint2 bh0, bl0, bh1, bl1;                                              \
        bf16_split2(BV0.x, BV0.y, bh0.x, bl0.x);                               \
        bf16_split2(BV0.z, BV0.w, bh0.y, bl0.y);                               \
        bf16_split2(BV1.x, BV1.y, bh1.x, bl1.x);                               \
        bf16_split2(BV1.z, BV1.w, bh1.y, bl1.y);                               \
        *(uint2*)&BSH[(2 * b_p) * GB_S + (b_c >> 1)] = bh0;                    \
        *(uint2*)&BSL[(2 * b_p) * GB_S + (b_c >> 1)] = bl0;                    \
        *(uint2*)&BSH[(2 * b_p + 1) * GB_S + (b_c >> 1)] = bh1;                \
        *(uint2*)&BSL[(2 * b_p + 1) * GB_S + (b_c >> 1)] = bl1;                \
    }

    {
        float4 av0 = *(const float4*)(Ap0);
        float4 av1 = *(const float4*)(Ap1);
        float4 bv0 = *(const float4*)(Bp0);
        float4 bv1 = *(const float4*)(Bp1);
        G_STORE_TILE(0, av0, av1, bv0, bv1);
    }
    __syncthreads();

    int buf = 0;
    for (int k0 = 0; k0 < K; k0 += 16) {
        const int kn = k0 + 16;
        const bool more = (kn < K);
        float4 av0, av1, bv0, bv1;
        if (more) {
            av0 = *(const float4*)(Ap0 + kn);
            av1 = *(const float4*)(Ap1 + kn);
            bv0 = *(const float4*)(Bp0 + (size_t)kn * N);
            bv1 = *(const float4*)(Bp1 + (size_t)kn * N);
        }

        const unsigned ash_b = smem_u32 + (buf * GBUF_W) * 4;
        const unsigned asl_b = ash_b + GA_W * 4;
        const unsigned bsh_b = ash_b + 2 * GA_W * 4;
        const unsigned bsl_b = bsh_b + GB_W * 4;

        unsigned ah[2][4], al[2][4], bh[8][2], bl[8][2];
        #pragma unroll
        for (int mf = 0; mf < 2; mf++) {
            const int m = wm * 32 + mf * 16 + a_lm_row;
            const unsigned off = (unsigned)(m * GA_S + a_lm_coff) * 4u;
            LDSM_X4(ah[mf][0], ah[mf][1], ah[mf][2], ah[mf][3], ash_b + off);
            LDSM_X4(al[mf][0], al[mf][1], al[mf][2], al[mf][3], asl_b + off);
        }
        #pragma unroll
        for (int np = 0; np < 4; np++) {
            const int n0 = wn * 64 + np * 16;
            const unsigned off =
                (unsigned)(b_lm_row * GB_S + (n0 >> 1) + b_lm_noff) * 4u;
            LDSM_X4_T(bh[2*np][0], bh[2*np][1], bh[2*np+1][0], bh[2*np+1][1],
                      bsh_b + off);
            LDSM_X4_T(bl[2*np][0], bl[2*np][1], bl[2*np+1][0], bl[2*np+1][1],
                      bsl_b + off);
        }

        #pragma unroll
        for (int mf = 0; mf < 2; mf++)
            #pragma unroll
            for (int nf = 0; nf < 8; nf++) {
                mma_bf16(acc[mf][nf], ah[mf], bh[nf]);
                mma_bf16(acc[mf][nf], ah[mf], bl[nf]);
                mma_bf16(acc[mf][nf], al[mf], bh[nf]);
            }

        if (more) {
            G_STORE_TILE(buf ^ 1, av0, av1, bv0, bv1);
            __syncthreads();
        }
        buf ^= 1;
    }
#undef G_STORE_TILE

    #pragma unroll
    for (int mf = 0; mf < 2; mf++) {
        #pragma unroll
        for (int nf = 0; nf < 8; nf++) {
            const int row = row0 + wm * 32 + mf * 16 + gid;
            const int col = col0 + wn * 64 + nf * 8 + 2 * tig;
            const float b0 = bias[col], b1 = bias[col + 1];
            float2 o0, o1;
            o0.x = acc[mf][nf][0] + b0;
            o0.y = acc[mf][nf][1] + b1;
            o1.x = acc[mf][nf][2] + b0;
            o1.y = acc[mf][nf][3] + b1;
            if (RESID) {
                const float2 r0 = *(const float2*)(resid + (size_t)row * N + col);
                const float2 r1 = *(const float2*)(resid + (size_t)(row + 8) * N + col);
                o0.x += r0.x; o0.y += r0.y;
                o1.x += r1.x; o1.y += r1.y;
            }
            *(float2*)(C + (size_t)row * N + col) = o0;
            *(float2*)(C + (size_t)(row + 8) * N + col) = o1;
        }
    }
}

// ---------------------------------------------------------------------------
// Tensor-core flash attention, causal + alibi. BR=128, BC=64, HD=128,
// 8 warps x 16-row bands (warp-local softmax).
// All fragment loads via ldmatrix:
//   Q: non-trans x4 on [r][k2] (GEMM-A pattern), 1 op/j.
//   K: non-trans x4 on [n][k2] (lane 4g+t -> row g word t = b-frag), 4 ops/j.
//   V: unpacked bf16 [k][n] stride 68, trans x4 (GEMM-B pattern), 8 ops/j.
// S = 1x bf16; P@V = bf16x3; P a-frag = lane's own S c-frag values (FA2 id).
// ---------------------------------------------------------------------------
#define BR 128
#define BC 64
#define QPS 68                        // Qp row stride (words), [128][68]
#define KPS 68                        // Kp row stride (words), [64][68]
#define VPS2 68                       // V plane k-row stride (words), [64][68]
#define QP_W (BR * QPS)               // 8704
#define KP_W (BC * KPS)               // 4352
#define VP2_W (64 * VPS2)             // 4352 per plane
#define AT_SMEM_BYTES ((QP_W + KP_W + 2 * VP2_W) * 4)   // ~87 KB

__global__ __launch_bounds__(256, 1) void flash_attn_mma(const float* __restrict__ alibi)
{
    extern __shared__ unsigned smu[];
    unsigned* Qp  = smu;                 // [BR][QPS] bf16x2 pairs (k-dim)
    unsigned* Kp  = Qp + QP_W;           // [BC][KPS] bf16x2 pairs (k-dim)
    unsigned* VsH = Kp + KP_W;           // [64][VPS2] bf16 hi, [k][n] unpacked
    unsigned* VsL = VsH + VP2_W;         // [64][VPS2] bf16 lo

    const unsigned at_u32  = (unsigned)__cvta_generic_to_shared(smu);
    const unsigned q_u32   = at_u32;
    const unsigned k_u32   = at_u32 + QP_W * 4;
    const unsigned vh_u32  = k_u32 + KP_W * 4;
    const unsigned vl_u32  = vh_u32 + VP2_W * 4;

    const int t    = threadIdx.x;
    const int lane = t & 31;
    const int w    = t >> 5;          // 0..7
    const int gid  = lane >> 2;       // 0..7
    const int tig  = lane & 3;        // 0..3
    const int band = w * 16;
    const int qt   = gridDim.x - 1 - blockIdx.x;   // heavy tiles first
    const int bh   = blockIdx.y;
    const int b    = bh >> 5;
    const int h    = bh & 31;
    const int q0   = qt * BR;

    const size_t rowbase = (size_t)(b * SEQ) * QKVN + (size_t)h * (3 * HD);
    const float* al = alibi + (size_t)bh * SEQ;

    const int kv_r  = t >> 5;              // 0..7 (warp id)
    const int kv_c4 = (t & 31) << 2;       // 0..124
    const int kv_k2 = kv_c4 >> 1;          // 0..62 even

    // ldmatrix per-lane address pieces
    const int q_lm_base = (band + (lane & 7) + ((lane >> 3) & 1) * 8) * QPS
                        + ((lane >> 4) << 2);                    // + 8j
    const int k_lm_n    = ((lane >> 4) << 3) + (lane & 7);       // + np*16
    const int k_lm_koff = ((lane >> 3) & 1) << 2;                // + 8j
    const int v_lm_kr   = (lane & 7) + (((lane >> 3) & 1) << 3); // + 16j
    const int v_lm_noff = (lane >> 4) << 2;                      // + np*8

    // Load Q tile: BR x HD -> packed bf16x2
    #pragma unroll
    for (int it = 0; it < 16; it++) {
        int idx = t + it * 256;            // 0..4095
        int r   = idx >> 5;                // 0..127
        int c4  = (idx & 31) << 2;         // 0..124
        float4 v = *(const float4*)(g_qkv + rowbase + (size_t)(q0 + r) * QKVN + c4);
        uint2 pw;
        pw.x = pack_bf16(v.x, v.y);
        pw.y = pack_bf16(v.z, v.w);
        *(uint2*)&Qp[r * QPS + (c4 >> 1)] = pw;
    }

    float O[16][4];
    #pragma unroll
    for (int nf = 0; nf < 16; nf++)
        #pragma unroll
        for (int r = 0; r < 4; r++) O[nf][r] = 0.0f;
    float m0 = -1e30f, m1 = -1e30f, l0 = 0.0f, l1 = 0.0f;

    float4 kp[8], vpa[4], vpb[4];
#define LOAD_KV(KBASE)                                                         \
    {                                                                          \
        _Pragma("unroll")                                                      \
        for (int it = 0; it < 8; it++) {                                       \
            const float* base = g_qkv + rowbase +                              \
                (size_t)((KBASE) + kv_r + it * 8) * QKVN;                      \
            kp[it] = *(const float4*)(base + HD + kv_c4);                      \
        }                                                                      \
        _Pragma("unroll")                                                      \
        for (int it = 0; it < 4; it++) {                                       \
            const int p = kv_r + it * 8;                                       \
            const float* vb = g_qkv + rowbase +                                \
                (size_t)((KBASE) + 2 * p) * QKVN + 2 * HD + kv_c4;             \
            vpa[it] = *(const float4*)(vb);                                    \
            vpb[it] = *(const float4*)(vb + QKVN);                             \
        }                                                                      \
    }

    LOAD_KV(0);   // prologue: tile 0 into registers

    const int kc_max = 2 * qt + 1;
    for (int kc = 0; kc <= kc_max; kc++) {
        const int kbase = kc * BC;
        __syncthreads();  // prev iter's K/V smem reads done (covers Q on iter 0)

        // K: packed bf16x2 along k. V: unpacked bf16 [k][n] hi/lo planes.
        #pragma unroll
        for (int it = 0; it < 8; it++) {
            const int r = kv_r + it * 8;
            uint2 kw;
            kw.x = pack_bf16(kp[it].x, kp[it].y);
            kw.y = pack_bf16(kp[it].z, kp[it].w);
            *(uint2*)&Kp[r * KPS + kv_k2] = kw;
        }
        #pragma unroll
        for (int it = 0; it < 4; it++) {
            const int p = kv_r + it * 8;
            uint2 hA, lA, hB, lB;
            bf16_split2(vpa[it].x, vpa[it].y, hA.x, lA.x);
            bf16_split2(vpa[it].z, vpa[it].w, hA.y, lA.y);
            bf16_split2(vpb[it].x, vpb[it].y, hB.x, lB.x);
            bf16_split2(vpb[it].z, vpb[it].w, hB.y, lB.y);
            *(uint2*)&VsH[(2 * p) * VPS2 + kv_k2] = hA;
            *(uint2*)&VsL[(2 * p) * VPS2 + kv_k2] = lA;
            *(uint2*)&VsH[(2 * p + 1) * VPS2 + kv_k2] = hB;
            *(uint2*)&VsL[(2 * p + 1) * VPS2 + kv_k2] = lB;
        }
        __syncthreads();

        if (kc < kc_max) LOAD_KV(kbase + BC);

        // --- S = Q @ K^T (1x bf16), rows band..band+15, cols 0..63 ---
        float S[8][4];
        #pragma unroll
        for (int nf = 0; nf < 8; nf++)
            #pragma unroll
            for (int r = 0; r < 4; r++) S[nf][r] = 0.0f;

        #pragma unroll
        for (int j = 0; j < 8; j++) {
            unsigned a[4];
            LDSM_X4(a[0], a[1], a[2], a[3],
                    q_u32 + (unsigned)(q_lm_base + 8 * j) * 4u);
            #pragma unroll
            for (int np = 0; np < 4; np++) {
                unsigned b4[4];
                LDSM_X4(b4[0], b4[1], b4[2], b4[3],
                        k_u32 + (unsigned)((k_lm_n + np * 16) * KPS
                                           + 8 * j + k_lm_koff) * 4u);
                mma_bf16(S[2*np],     a, b4);
                mma_bf16(S[2*np + 1], a, b4 + 2);
            }
        }

        // --- alibi + scale + causal mask + online softmax (warp-local) ---
        const int qr0 = q0 + band + gid;
        const int qr1 = qr0 + 8;
        float mx0 = -1e30f, mx1 = -1e30f;
        if (kc < 2 * qt) {
            #pragma unroll
            for (int nf = 0; nf < 8; nf++) {
                const int c0 = kbase + nf * 8 + 2 * tig;
                const float a0 = al[c0], a1 = al[c0 + 1];
                S[nf][0] = fmaf(INV_NORM, S[nf][0], a0);
                S[nf][1] = fmaf(INV_NORM, S[nf][1], a1);
                S[nf][2] = fmaf(INV_NORM, S[nf][2], a0);
                S[nf][3] = fmaf(INV_NORM, S[nf][3], a1);
                mx0 = fmaxf(mx0, fmaxf(S[nf][0], S[nf][1]));
                mx1 = fmaxf(mx1, fmaxf(S[nf][2], S[nf][3]));
            }
        } else {
            #pragma unroll
            for (int nf = 0; nf < 8; nf++) {
                const int c0 = kbase + nf * 8 + 2 * tig;
                const float a0 = al[c0], a1 = al[c0 + 1];
                S[nf][0] = (c0     <= qr0) ? fmaf(INV_NORM, S[nf][0], a0) : -1e30f;
                S[nf][1] = (c0 + 1 <= qr0) ? fmaf(INV_NORM, S[nf][1], a1) : -1e30f;
                S[nf][2] = (c0     <= qr1) ? fmaf(INV_NORM, S[nf][2], a0) : -1e30f;
                S[nf][3] = (c0 + 1 <= qr1) ? fmaf(INV_NORM, S[nf][3], a1) : -1e30f;
                mx0 = fmaxf(mx0, fmaxf(S[nf][0], S[nf][1]));
                mx1 = fmaxf(mx1, fmaxf(S[nf][2], S[nf][3]));
            }
        }
        mx0 = fmaxf(mx0, __shfl_xor_sync(0xffffffffu, mx0, 1));
        mx0 = fmaxf(mx0, __shfl_xor_sync(0xffffffffu, mx0, 2));
        mx1 = fmaxf(mx1, __shfl_xor_sync(0xffffffffu, mx1, 1));
        mx1 = fmaxf(mx1, __shfl_xor_sync(0xffffffffu, mx1, 2));

        const float mn0 = fmaxf(m0, mx0);
        const float mn1 = fmaxf(m1, mx1);
        const float corr0 = __expf(m0 - mn0);
        const float corr1 = __expf(m1 - mn1);

        float rs0 = 0.0f, rs1 = 0.0f;
        #pragma unroll
        for (int nf = 0; nf < 8; nf++) {
            S[nf][0] = __expf(S[nf][0] - mn0);
            S[nf][1] = __expf(S[nf][1] - mn0);
            S[nf][2] = __expf(S[nf][2] - mn1);
            S[nf][3] = __expf(S[nf][3] - mn1);
            rs0 += S[nf][0] + S[nf][1];
            rs1 += S[nf][2] + S[nf][3];
        }
        rs0 += __shfl_xor_sync(0xffffffffu, rs0, 1);
        rs0 += __shfl_xor_sync(0xffffffffu, rs0, 2);
        rs1 += __shfl_xor_sync(0xffffffffu, rs1, 1);
        rs1 += __shfl_xor_sync(0xffffffffu, rs1, 2);

        l0 = l0 * corr0 + rs0; m0 = mn0;
        l1 = l1 * corr1 + rs1; m1 = mn1;
        #pragma unroll
        for (int nf = 0; nf < 16; nf++) {
            O[nf][0] *= corr0; O[nf][1] *= corr0;
            O[nf][2] *= corr1; O[nf][3] *= corr1;
        }

        // --- O += P @ V (bf16x3); P a-frag = lane's own S values ---
        #pragma unroll
        for (int j = 0; j < 4; j++) {
            unsigned aph[4], apl[4];
            bf16_split2(S[2*j][0],   S[2*j][1],   aph[0], apl[0]);
            bf16_split2(S[2*j][2],   S[2*j][3],   aph[1], apl[1]);
            bf16_split2(S[2*j+1][0], S[2*j+1][1], aph[2], apl[2]);
            bf16_split2(S[2*j+1][2], S[2*j+1][3], aph[3], apl[3]);
            const unsigned krow_off = (unsigned)((16 * j + v_lm_kr) * VPS2) * 4u;
            #pragma unroll
            for (int np = 0; np < 8; np++) {
                const unsigned noff = (unsigned)(np * 8 + v_lm_noff) * 4u;
                unsigned bh4[4], bl4[4];
                LDSM_X4_T(bh4[0], bh4[1], bh4[2], bh4[3], vh_u32 + krow_off + noff);
                LDSM_X4_T(bl4[0], bl4[1], bl4[2], bl4[3], vl_u32 + krow_off + noff);
                mma_bf16(O[2*np],     aph, bh4);
                mma_bf16(O[2*np],     aph, bl4);
                mma_bf16(O[2*np],     apl, bh4);
                mma_bf16(O[2*np + 1], aph, bh4 + 2);
                mma_bf16(O[2*np + 1], aph, bl4 + 2);
                mma_bf16(O[2*np + 1], apl, bh4 + 2);
            }
        }
    }
#undef LOAD_KV

    // Normalize and store ctx
    const float inv0 = 1.0f / l0;
    const float inv1 = 1.0f / l1;
    const size_t d0base = (size_t)(b * SEQ + q0 + band + gid) * HID + h * HD;
    const size_t d1base = (size_t)(b * SEQ + q0 + band + gid + 8) * HID + h * HD;
    #pragma unroll
    for (int nf = 0; nf < 16; nf++) {
        const int col = nf * 8 + 2 * tig;
        *(float2*)(g_ctx + d0base + col) = make_float2(O[nf][0] * inv0, O[nf][1] * inv0);
        *(float2*)(g_ctx + d1base + col) = make_float2(O[nf][2] * inv1, O[nf][3] * inv1);
    }
}

// ---------------------------------------------------------------------------
// Launch
// ---------------------------------------------------------------------------
extern "C" void kernel_launch(void* const* d_in, const int* in_sizes, int n_in,
                              void* d_out, int out_size)
{
    const float* hidden   = (const float*)d_in[0];
    const float* residual = (const float*)d_in[1];
    const float* alibi    = (const float*)d_in[2];
    // d_in[3] attention_mask: fixed causal triu — computed analytically, not read
    const float* W_qkv    = (const float*)d_in[4];
    const float* b_qkv    = (const float*)d_in[5];
    const float* W_dense  = (const float*)d_in[6];
    const float* b_dense  = (const float*)d_in[7];
    float* out = (float*)d_out;

    float* qkv_ptr = nullptr;
    float* ctx_ptr = nullptr;
    cudaGetSymbolAddress((void**)&qkv_ptr, g_qkv);
    cudaGetSymbolAddress((void**)&ctx_ptr, g_ctx);

    cudaFuncSetAttribute(bf16_gemm<false>, cudaFuncAttributeMaxDynamicSharedMemorySize,
                         GEMM_SMEM_BYTES);
    cudaFuncSetAttribute(bf16_gemm<true>, cudaFuncAttributeMaxDynamicSharedMemorySize,
                         GEMM_SMEM_BYTES);
    cudaFuncSetAttribute(flash_attn_mma, cudaFuncAttributeMaxDynamicSharedMemorySize,
                         AT_SMEM_BYTES);

    // 1) QKV projection: [2048,4096] @ [4096,12288] + b_qkv
    {
        dim3 grid(QKVN / 128, MROWS / 128);
        bf16_gemm<false><<<grid, 256, GEMM_SMEM_BYTES>>>(hidden, W_qkv, b_qkv, nullptr,
                                                         qkv_ptr, MROWS, QKVN, HID);
    }

    // 2) Attention (64 heads x 8 query tiles of 128 rows)
    {
        dim3 grid(SEQ / BR, BATCH * NHEAD);
        flash_attn_mma<<<grid, 256, AT_SMEM_BYTES>>>(alibi);
    }

    // 3) Dense projection + bias + residual
    {
        dim3 grid(HID / 128, MROWS / 128);
        bf16_gemm<true><<<grid, 256, GEMM_SMEM_BYTES>>>(ctx_ptr, W_dense, b_dense, residual,
                                                        out, MROWS, HID, HID);
    }
}